// round 1
// baseline (speedup 1.0000x reference)
#include <cuda_runtime.h>
#include <cstdint>

#define NNODES 65536
#define NPART  128
#define EPSV   1e-8f
#define BIGV   999.0f

// ---- output layout (flattened f32, reference tuple order) ----
#define OFF_RMS    0
#define OFF_RMSQ   128
#define OFF_NP     256
#define OFF_NN     384
#define OFF_RMSG   1024
#define OFF_RMSQG  1025
#define OFF_NG     1026
#define OFF_NNG    1027
#define OFF_DB     1032
#define OFF_NNODE  1033
#define OFF_DIST   66569
#define OFF_BEL    8455177

// ---- device scratch (static globals only; no allocations) ----
// g_scal: [0]=sum q, [1]=sum q^2, [2]=A=sum q^2|x|^2, [3..5]=C=sum q^2 x, [6]=sum |x|^2
__device__ double g_scal[7];
__device__ double g_sumdx2[NPART];
__device__ int    g_cnt[NPART];
__device__ int    g_ncond;
__device__ float4 g_condx[NNODES];

__device__ __forceinline__ float fsqrt_ap(float x) {
    float r; asm("sqrt.approx.f32 %0, %1;" : "=f"(r) : "f"(x)); return r;
}

// ---------------------------------------------------------------------------
__global__ void k_init() {
    int t = threadIdx.x;
    if (t < 7)     g_scal[t] = 0.0;
    if (t < NPART) { g_sumdx2[t] = 0.0; g_cnt[t] = 0; }
    if (t == 0)    g_ncond = 0;
}

// ---------------------------------------------------------------------------
// Main pass: one node per thread, loop all 128 particles with max_x in SMEM.
// Writes dist_edge + belongs_edge (coalesced per-p rows), accumulates:
//   - per-parent sum dx^2 and count  (shared bins -> double atomics)
//   - 7 global scalars (warp reduce -> double atomics)
//   - compacted cond-point list for the top-5 kernel
__global__ void __launch_bounds__(128)
k_main(const float* __restrict__ x, const float* __restrict__ q,
       const float* __restrict__ ic, const float* __restrict__ maxx,
       const int* __restrict__ parent, float* __restrict__ out) {
    __shared__ float sm0[NPART], sm1[NPART], sm2[NPART];
    __shared__ float sdx2[NPART];
    __shared__ int   scnt[NPART];

    const int t = threadIdx.x;
    sm0[t] = maxx[3 * t + 0];
    sm1[t] = maxx[3 * t + 1];
    sm2[t] = maxx[3 * t + 2];
    sdx2[t] = 0.f; scnt[t] = 0;
    __syncthreads();

    const int n = blockIdx.x * 128 + t;
    const float x0 = x[3 * n + 0], x1 = x[3 * n + 1], x2 = x[3 * n + 2];
    const float qv = q[n], icv = ic[n];
    const int   pa = parent[n];
    const float nx2 = fmaf(x2, x2, fmaf(x1, x1, x0 * x0));
    const float q2  = qv * qv;

    // parent-particle contribution (belongs is one-hot)
    {
        float d0 = x0 - sm0[pa], d1 = x1 - sm1[pa], d2 = x2 - sm2[pa];
        float dd = fmaf(d2, d2, fmaf(d1, d1, d0 * d0));
        atomicAdd(&sdx2[pa], dd);
        atomicAdd(&scnt[pa], 1);
    }

    // compact cond points
    if (icv > 0.f) {
        int pos = atomicAdd(&g_ncond, 1);
        g_condx[pos] = make_float4(x0, x1, x2, 0.f);
    }

    // global scalar sums (double-accumulated)
    {
        float v[7] = { qv, q2, q2 * nx2, q2 * x0, q2 * x1, q2 * x2, nx2 };
        #pragma unroll
        for (int k = 0; k < 7; k++) {
            float s = v[k];
            #pragma unroll
            for (int o = 16; o > 0; o >>= 1) s += __shfl_xor_sync(0xffffffffu, s, o);
            v[k] = s;
        }
        if ((t & 31) == 0) {
            #pragma unroll
            for (int k = 0; k < 7; k++) atomicAdd(&g_scal[k], (double)v[k]);
        }
    }

    // streaming writes: dist + belongs for all 128 particles
    float* dptr = out + OFF_DIST + n;
    float* bptr = out + OFF_BEL  + n;
    #pragma unroll 4
    for (int p = 0; p < NPART; p++) {
        float d0 = x0 - sm0[p], d1 = x1 - sm1[p], d2 = x2 - sm2[p];
        float dd = fmaf(d2, d2, fmaf(d1, d1, d0 * d0));
        *dptr = fsqrt_ap(dd);
        *bptr = (pa == p) ? 1.0f : 0.0f;
        dptr += NNODES; bptr += NNODES;
    }

    __syncthreads();
    atomicAdd(&g_sumdx2[t], (double)sdx2[t]);
    atomicAdd(&g_cnt[t], scnt[t]);
}

// ---------------------------------------------------------------------------
// Top-5 smallest cond distances. Block p in [0,128): particle p; block 128: global (m=0).
__global__ void __launch_bounds__(256)
k_top5(const float* __restrict__ maxx, float* __restrict__ out) {
    const int p = blockIdx.x;
    float m0 = 0.f, m1 = 0.f, m2 = 0.f;
    if (p < NPART) { m0 = maxx[3 * p]; m1 = maxx[3 * p + 1]; m2 = maxx[3 * p + 2]; }
    const int nc = g_ncond;

    float tv[5] = { BIGV, BIGV, BIGV, BIGV, BIGV };
    for (int i = threadIdx.x; i < nc; i += 256) {
        float4 c = g_condx[i];
        float d0 = c.x - m0, d1 = c.y - m1, d2 = c.z - m2;
        float d = fsqrt_ap(fmaf(d2, d2, fmaf(d1, d1, d0 * d0)));
        if (d >= EPSV && d < tv[4]) {
            tv[4] = d;
            #pragma unroll
            for (int k = 4; k > 0; k--)
                if (tv[k] < tv[k - 1]) { float tmp = tv[k - 1]; tv[k - 1] = tv[k]; tv[k] = tmp; }
        }
    }

    __shared__ float s[256 * 5];
    #pragma unroll
    for (int k = 0; k < 5; k++) s[threadIdx.x * 5 + k] = tv[k];
    __syncthreads();

    for (int str = 128; str >= 1; str >>= 1) {
        if (threadIdx.x < (unsigned)str) {
            float a[5], b[5], r[5];
            #pragma unroll
            for (int k = 0; k < 5; k++) { a[k] = s[threadIdx.x * 5 + k]; b[k] = s[(threadIdx.x + str) * 5 + k]; }
            int ia = 0, ib = 0;
            #pragma unroll
            for (int k = 0; k < 5; k++) r[k] = (a[ia] <= b[ib]) ? a[ia++] : b[ib++];
            #pragma unroll
            for (int k = 0; k < 5; k++) s[threadIdx.x * 5 + k] = r[k];
        }
        __syncthreads();
    }

    if (threadIdx.x == 0) {
        float* dst = (p < NPART) ? (out + OFF_NN + p * 5) : (out + OFF_NNG);
        #pragma unroll
        for (int k = 0; k < 5; k++) dst[k] = s[k];
    }
}

// ---------------------------------------------------------------------------
__global__ void __launch_bounds__(128)
k_fin(const float* __restrict__ maxx, const float* __restrict__ maxq,
      float* __restrict__ out) {
    __shared__ float srms[NPART], sx0[NPART], sx1[NPART], sx2[NPART], sred[NPART];
    const int p = threadIdx.x;

    const double sumq = g_scal[0], Bq = g_scal[1], A = g_scal[2];
    const double C0 = g_scal[3], C1 = g_scal[4], C2 = g_scal[5], snx2 = g_scal[6];

    const float m0 = maxx[3 * p], m1 = maxx[3 * p + 1], m2 = maxx[3 * p + 2];
    const int   cnt = g_cnt[p];
    const double Npd = (double)cnt;
    const double mp2 = (double)m0 * m0 + (double)m1 * m1 + (double)m2 * m2;
    const double S = A + mp2 * Bq - 2.0 * ((double)m0 * C0 + (double)m1 * C1 + (double)m2 * C2);
    const float rms = (float)sqrt(g_sumdx2[p] / Npd);
    const double mq = (double)maxq[p];
    // particle-case sum_q quirk: sum over the entire [P,N] q mailbox = P * sum(q)
    const float rmsq = (float)sqrt(mq * mq * S / (Npd * ((double)NPART * sumq)));

    out[OFF_RMS  + p] = rms;
    out[OFF_RMSQ + p] = rmsq;
    out[OFF_NP   + p] = (float)cnt;

    srms[p] = rms; sx0[p] = m0; sx1[p] = m1; sx2[p] = m2;
    __syncthreads();

    // Davies-Bouldin: db = mean_i max_j (rms_i+rms_j)/||mi-mj||^2  (M2==0 -> 0)
    float maxR = 0.f;
    for (int j = 0; j < NPART; j++) {
        float e0 = sx0[p] - sx0[j], e1 = sx1[p] - sx1[j], e2 = sx2[p] - sx2[j];
        float M2 = fmaf(e2, e2, fmaf(e1, e1, e0 * e0));
        if (M2 > 0.f) maxR = fmaxf(maxR, (srms[p] + srms[j]) / M2);
    }
    sred[p] = maxR;
    __syncthreads();
    for (int str = 64; str >= 1; str >>= 1) {
        if (p < str) sred[p] += sred[p + str];
        __syncthreads();
    }
    if (p == 0) {
        out[OFF_DB]    = sred[0] / (float)NPART;
        out[OFF_RMSG]  = (float)sqrt(snx2 / (double)NNODES);
        out[OFF_RMSQG] = (float)sqrt(A / ((double)NNODES * sumq));
        out[OFF_NG]    = (float)NNODES;
    }
}

// ---------------------------------------------------------------------------
__global__ void __launch_bounds__(256)
k_nnode(const int* __restrict__ parent, float* __restrict__ out) {
    int n = blockIdx.x * 256 + threadIdx.x;
    out[OFF_NNODE + n] = (float)g_cnt[parent[n]];
}

// ---------------------------------------------------------------------------
extern "C" void kernel_launch(void* const* d_in, const int* in_sizes, int n_in,
                              void* d_out, int out_size) {
    const float* x      = (const float*)d_in[0];
    const float* q      = (const float*)d_in[1];
    const float* ic     = (const float*)d_in[2];
    const float* maxx   = (const float*)d_in[5];
    const float* maxq   = (const float*)d_in[6];
    const int*   parent = (const int*)d_in[8];
    float* out = (float*)d_out;

    k_init <<<1, 128>>>();
    k_main <<<NNODES / 128, 128>>>(x, q, ic, maxx, parent, out);
    k_top5 <<<NPART + 1, 256>>>(maxx, out);
    k_fin  <<<1, 128>>>(maxx, maxq, out);
    k_nnode<<<NNODES / 256, 256>>>(parent, out);
    (void)in_sizes; (void)n_in; (void)out_size;
}

// round 2
// speedup vs baseline: 1.6316x; 1.6316x over previous
#include <cuda_runtime.h>
#include <cstdint>

#define NNODES 65536
#define NPART  128
#define EPSV   1e-8f
#define BIGV   999.0f

// ---- output layout (flattened f32, reference tuple order) ----
#define OFF_RMS    0
#define OFF_RMSQ   128
#define OFF_NP     256
#define OFF_NN     384
#define OFF_RMSG   1024
#define OFF_RMSQG  1025
#define OFF_NG     1026
#define OFF_NNG    1027
#define OFF_DB     1032
#define OFF_NNODE  1033
#define OFF_DIST   66569
#define OFF_BEL    8455177

// belongs zero-fill geometry: region = [OFF_BEL, OFF_BEL + 128*65536)
// OFF_BEL % 4 == 1 -> head of 3 floats, 2097151 aligned float4s, tail of 1 float
#define BEL_Q4     2097151
#define NTHREADS_M 32768   // 256 blocks * 128 threads

// ---- device scratch ----
// g_scal: [0]=sum q, [1]=sum q^2, [2]=A=sum q^2|x|^2, [3..5]=C=sum q^2 x, [6]=sum |x|^2
__device__ double g_scal[7];
__device__ double g_sumdx2[NPART];
__device__ int    g_cnt[NPART];
__device__ int    g_ncond;
__device__ float4 g_condx[NNODES];

__device__ __forceinline__ float fsqrt_ap(float x) {
    float r; asm("sqrt.approx.f32 %0, %1;" : "=f"(r) : "f"(x)); return r;
}

// ---------------------------------------------------------------------------
__global__ void k_init() {
    int t = threadIdx.x;
    if (t < 7)     g_scal[t] = 0.0;
    if (t < NPART) { g_sumdx2[t] = 0.0; g_cnt[t] = 0; }
    if (t == 0)    g_ncond = 0;
}

// ---------------------------------------------------------------------------
// Main pass: 256 blocks x 128 threads. Thread g handles node pair (2g+1, 2g+2)
// so dist stores are 8B-aligned float2 (OFF_DIST is odd). The last thread
// handles the two edge nodes {0, 65535} with scalar stores.
// Also: flat aligned float4 zero-fill of the belongs region, per-parent
// sum-dx^2/count bins, 7 global scalar sums, cond-point compaction.
__global__ void __launch_bounds__(128)
k_main(const float* __restrict__ x, const float* __restrict__ q,
       const float* __restrict__ ic, const float* __restrict__ maxx,
       const int* __restrict__ parent, float* __restrict__ out) {
    __shared__ float sm0[NPART], sm1[NPART], sm2[NPART];
    __shared__ float sdx2[NPART];
    __shared__ int   scnt[NPART];
    __shared__ int   s_cc, s_base;
    __shared__ float4 s_cond[256];

    const int t = threadIdx.x;
    sm0[t] = maxx[3 * t + 0];
    sm1[t] = maxx[3 * t + 1];
    sm2[t] = maxx[3 * t + 2];
    sdx2[t] = 0.f; scnt[t] = 0;
    if (t == 0) s_cc = 0;
    __syncthreads();

    const int  g = blockIdx.x * 128 + t;
    const bool paired = (g < NTHREADS_M - 1);
    const int  na = paired ? 2 * g + 1 : 0;
    const int  nb = paired ? 2 * g + 2 : NNODES - 1;

    const float a0 = x[3 * na], a1 = x[3 * na + 1], a2 = x[3 * na + 2];
    const float b0 = x[3 * nb], b1 = x[3 * nb + 1], b2 = x[3 * nb + 2];
    const float qa = q[na], qb = q[nb];
    const float ia = ic[na], ib = ic[nb];
    const int   pa = parent[na], pb = parent[nb];
    const float nxa = fmaf(a2, a2, fmaf(a1, a1, a0 * a0));
    const float nxb = fmaf(b2, b2, fmaf(b1, b1, b0 * b0));
    const float q2a = qa * qa, q2b = qb * qb;

    // parent-particle contributions (belongs is one-hot per node)
    {
        float d0 = a0 - sm0[pa], d1 = a1 - sm1[pa], d2 = a2 - sm2[pa];
        atomicAdd(&sdx2[pa], fmaf(d2, d2, fmaf(d1, d1, d0 * d0)));
        atomicAdd(&scnt[pa], 1);
        d0 = b0 - sm0[pb]; d1 = b1 - sm1[pb]; d2 = b2 - sm2[pb];
        atomicAdd(&sdx2[pb], fmaf(d2, d2, fmaf(d1, d1, d0 * d0)));
        atomicAdd(&scnt[pb], 1);
    }

    // cond-point compaction into shared
    if (ia > 0.f) { int p_ = atomicAdd(&s_cc, 1); s_cond[p_] = make_float4(a0, a1, a2, 0.f); }
    if (ib > 0.f) { int p_ = atomicAdd(&s_cc, 1); s_cond[p_] = make_float4(b0, b1, b2, 0.f); }

    // global scalar sums (warp reduce -> double atomics)
    {
        float v[7] = { qa + qb, q2a + q2b,
                       fmaf(q2a, nxa, q2b * nxb),
                       fmaf(q2a, a0, q2b * b0),
                       fmaf(q2a, a1, q2b * b1),
                       fmaf(q2a, a2, q2b * b2),
                       nxa + nxb };
        #pragma unroll
        for (int k = 0; k < 7; k++) {
            float s = v[k];
            #pragma unroll
            for (int o = 16; o > 0; o >>= 1) s += __shfl_xor_sync(0xffffffffu, s, o);
            v[k] = s;
        }
        if ((t & 31) == 0) {
            #pragma unroll
            for (int k = 0; k < 7; k++) atomicAdd(&g_scal[k], (double)v[k]);
        }
    }

    // ---- dist_edge: 128 rows, float2 per thread (aligned since na is odd) ----
    float* dbase = out + OFF_DIST;
    if (paired) {
        #pragma unroll 4
        for (int p = 0; p < NPART; p++) {
            float m0 = sm0[p], m1 = sm1[p], m2 = sm2[p];
            float d0 = a0 - m0, d1 = a1 - m1, d2 = a2 - m2;
            float da = fsqrt_ap(fmaf(d2, d2, fmaf(d1, d1, d0 * d0)));
            d0 = b0 - m0; d1 = b1 - m1; d2 = b2 - m2;
            float db_ = fsqrt_ap(fmaf(d2, d2, fmaf(d1, d1, d0 * d0)));
            *(float2*)(dbase + p * NNODES + na) = make_float2(da, db_);
        }
    } else {
        for (int p = 0; p < NPART; p++) {
            float m0 = sm0[p], m1 = sm1[p], m2 = sm2[p];
            float d0 = a0 - m0, d1 = a1 - m1, d2 = a2 - m2;
            dbase[p * NNODES + na] = fsqrt_ap(fmaf(d2, d2, fmaf(d1, d1, d0 * d0)));
            d0 = b0 - m0; d1 = b1 - m1; d2 = b2 - m2;
            dbase[p * NNODES + nb] = fsqrt_ap(fmaf(d2, d2, fmaf(d1, d1, d0 * d0)));
        }
    }

    // ---- belongs_edge zero-fill: flat aligned float4 stores ----
    {
        const float4 z4 = make_float4(0.f, 0.f, 0.f, 0.f);
        float4* zb = (float4*)(out + OFF_BEL + 3);
        for (int i = g; i < BEL_Q4; i += NTHREADS_M) zb[i] = z4;
        if (!paired) {
            out[OFF_BEL + 0] = 0.f; out[OFF_BEL + 1] = 0.f; out[OFF_BEL + 2] = 0.f;
            out[OFF_BEL + NPART * NNODES - 1] = 0.f;
        }
    }

    // flush cond compaction (one global atomic per block, coalesced copy)
    __syncthreads();
    if (t == 0) s_base = (s_cc > 0) ? atomicAdd(&g_ncond, s_cc) : 0;
    __syncthreads();
    for (int i = t; i < s_cc; i += 128) g_condx[s_base + i] = s_cond[i];

    // flush per-particle bins
    atomicAdd(&g_sumdx2[t], (double)sdx2[t]);
    atomicAdd(&g_cnt[t], scnt[t]);
}

// ---------------------------------------------------------------------------
// Fused tail: blocks 0..128 -> top-5 (receiver r = blockIdx, r==128 is global
// with m=0); block 129 -> finalize scalars/rms/db; blocks 130..385 -> N_node
// gather + belongs one-scatter.
__global__ void __launch_bounds__(256)
k_post(const float* __restrict__ maxx, const float* __restrict__ maxq,
       const int* __restrict__ parent, float* __restrict__ out) {
    const int b = blockIdx.x, t = threadIdx.x;

    if (b < NPART + 1) {
        // ------------- top-5 smallest cond distances -------------
        float m0 = 0.f, m1 = 0.f, m2 = 0.f;
        if (b < NPART) { m0 = maxx[3 * b]; m1 = maxx[3 * b + 1]; m2 = maxx[3 * b + 2]; }
        const int nc = g_ncond;

        float tv[5] = { BIGV, BIGV, BIGV, BIGV, BIGV };
        for (int i = t; i < nc; i += 256) {
            float4 c = g_condx[i];
            float d0 = c.x - m0, d1 = c.y - m1, d2 = c.z - m2;
            float d = fsqrt_ap(fmaf(d2, d2, fmaf(d1, d1, d0 * d0)));
            if (d >= EPSV && d < tv[4]) {
                tv[4] = d;
                #pragma unroll
                for (int k = 4; k > 0; k--)
                    if (tv[k] < tv[k - 1]) { float tmp = tv[k - 1]; tv[k - 1] = tv[k]; tv[k] = tmp; }
            }
        }

        __shared__ float s[256 * 5];
        #pragma unroll
        for (int k = 0; k < 5; k++) s[t * 5 + k] = tv[k];
        __syncthreads();
        for (int str = 128; str >= 1; str >>= 1) {
            if (t < str) {
                float A[5], B[5], R[5];
                #pragma unroll
                for (int k = 0; k < 5; k++) { A[k] = s[t * 5 + k]; B[k] = s[(t + str) * 5 + k]; }
                int ja = 0, jb = 0;
                #pragma unroll
                for (int k = 0; k < 5; k++) R[k] = (A[ja] <= B[jb]) ? A[ja++] : B[jb++];
                #pragma unroll
                for (int k = 0; k < 5; k++) s[t * 5 + k] = R[k];
            }
            __syncthreads();
        }
        if (t == 0) {
            float* dst = (b < NPART) ? (out + OFF_NN + b * 5) : (out + OFF_NNG);
            #pragma unroll
            for (int k = 0; k < 5; k++) dst[k] = s[k];
        }
    } else if (b == NPART + 1) {
        // ------------- finalize -------------
        __shared__ float srms[NPART], sx0[NPART], sx1[NPART], sx2[NPART], sred[NPART];
        const double sumq = g_scal[0], Bq = g_scal[1], A = g_scal[2];
        const double C0 = g_scal[3], C1 = g_scal[4], C2 = g_scal[5], snx2 = g_scal[6];

        if (t < NPART) {
            const float m0 = maxx[3 * t], m1 = maxx[3 * t + 1], m2 = maxx[3 * t + 2];
            const int   cnt = g_cnt[t];
            const double Npd = (double)cnt;
            const double mp2 = (double)m0 * m0 + (double)m1 * m1 + (double)m2 * m2;
            const double S = A + mp2 * Bq - 2.0 * ((double)m0 * C0 + (double)m1 * C1 + (double)m2 * C2);
            const float rms = (float)sqrt(g_sumdx2[t] / Npd);
            const double mq = (double)maxq[t];
            // particle-case sum_q quirk: whole [P,N] mailbox = P * sum(q)
            const float rmsq = (float)sqrt(mq * mq * S / (Npd * ((double)NPART * sumq)));
            out[OFF_RMS  + t] = rms;
            out[OFF_RMSQ + t] = rmsq;
            out[OFF_NP   + t] = (float)cnt;
            srms[t] = rms; sx0[t] = m0; sx1[t] = m1; sx2[t] = m2;
        }
        __syncthreads();

        if (t < NPART) {
            float maxR = 0.f;
            for (int j = 0; j < NPART; j++) {
                float e0 = sx0[t] - sx0[j], e1 = sx1[t] - sx1[j], e2 = sx2[t] - sx2[j];
                float M2 = fmaf(e2, e2, fmaf(e1, e1, e0 * e0));
                if (M2 > 0.f) maxR = fmaxf(maxR, (srms[t] + srms[j]) / M2);
            }
            sred[t] = maxR;
        }
        __syncthreads();
        for (int str = 64; str >= 1; str >>= 1) {
            if (t < str) sred[t] += sred[t + str];
            __syncthreads();
        }
        if (t == 0) {
            out[OFF_DB]    = sred[0] / (float)NPART;
            out[OFF_RMSG]  = (float)sqrt(snx2 / (double)NNODES);
            out[OFF_RMSQG] = (float)sqrt(A / ((double)NNODES * sumq));
            out[OFF_NG]    = (float)NNODES;
        }
    } else {
        // ------------- N_node gather + belongs one-scatter -------------
        const int n = (b - (NPART + 2)) * 256 + t;
        const int pa = parent[n];
        out[OFF_NNODE + n] = (float)g_cnt[pa];
        out[OFF_BEL + pa * NNODES + n] = 1.0f;
    }
}

// ---------------------------------------------------------------------------
extern "C" void kernel_launch(void* const* d_in, const int* in_sizes, int n_in,
                              void* d_out, int out_size) {
    const float* x      = (const float*)d_in[0];
    const float* q      = (const float*)d_in[1];
    const float* ic     = (const float*)d_in[2];
    const float* maxx   = (const float*)d_in[5];
    const float* maxq   = (const float*)d_in[6];
    const int*   parent = (const int*)d_in[8];
    float* out = (float*)d_out;

    k_init<<<1, 128>>>();
    k_main<<<256, 128>>>(x, q, ic, maxx, parent, out);
    k_post<<<NPART + 2 + NNODES / 256, 256>>>(maxx, maxq, parent, out);
    (void)in_sizes; (void)n_in; (void)out_size;
}